// round 13
// baseline (speedup 1.0000x reference)
#include <cuda_runtime.h>
#include <cuda_bf16.h>
#include <cstdint>

#define NROWS 10000
#define NFEAT 3000
#define NHID  32
#define KCLUS 10

#define NSPLIT1 3
#define NSPLIT2 4

#define BSTR 72                       // bf16 elems per B smem row (144 B stride)
#define BUFBYTES (32 * BSTR * 2)      // one B buffer: 4608 B

// Partial-sum scratch (plain STG, no zeroing: every slot overwritten each run)
__device__ __align__(16) float g_sup_part[NSPLIT1][NROWS * NHID];
__device__ __align__(16) float g_support[NROWS * NHID];
__device__ __align__(16) float g_z_part[NSPLIT2][NROWS * NHID];

__device__ __forceinline__ uint32_t s2u(const void* p) {
    uint32_t a;
    asm("{ .reg .u64 t; cvta.to.shared.u64 t, %1; cvt.u32.u64 %0, t; }" : "=r"(a) : "l"(p));
    return a;
}

// fp32 pair -> packed bf16 hi pair + bf16 residual pair
__device__ __forceinline__ void split2(float x, float y, uint32_t& h, uint32_t& l) {
    __nv_bfloat162 hb = __floats2bfloat162_rn(x, y);
    float2 hf = __bfloat1622float2(hb);
    __nv_bfloat162 lb = __floats2bfloat162_rn(x - hf.x, y - hf.y);
    h = *reinterpret_cast<uint32_t*>(&hb);
    l = *reinterpret_cast<uint32_t*>(&lb);
}

#define MMA_BF16(dd, a, b0, b1)                                              \
    asm volatile(                                                            \
        "mma.sync.aligned.m16n8k16.row.col.f32.bf16.bf16.f32 "               \
        "{%0,%1,%2,%3}, {%4,%5,%6,%7}, {%8,%9}, {%0,%1,%2,%3};"              \
        : "+f"(dd[0]), "+f"(dd[1]), "+f"(dd[2]), "+f"(dd[3])                 \
        : "r"(a[0]), "r"(a[1]), "r"(a[2]), "r"(a[3]), "r"(b0), "r"(b1))

#define LDSM4(r0, r1, r2, r3, addr)                                          \
    asm volatile(                                                            \
        "ldmatrix.sync.aligned.m8n8.x4.shared.b16 {%0,%1,%2,%3}, [%4];"      \
        : "=r"(r0), "=r"(r1), "=r"(r2), "=r"(r3) : "r"(addr))

// ---------------------------------------------------------------------------
// g_support = sum of NSPLIT1 gemm1 partials (L2-resident, trivially fast)
// ---------------------------------------------------------------------------
__global__ __launch_bounds__(256)
void reduce_sup() {
    int i = blockIdx.x * blockDim.x + threadIdx.x;
    if (i < (NROWS * NHID) / 4) {
        float4 s = ((const float4*)g_sup_part[0])[i];
#pragma unroll
        for (int p = 1; p < NSPLIT1; p++) {
            float4 t = ((const float4*)g_sup_part[p])[i];
            s.x += t.x; s.y += t.y; s.z += t.z; s.w += t.w;
        }
        ((float4*)g_support)[i] = s;
    }
}

// ---------------------------------------------------------------------------
// Cpart[M,32] = A[M,K_slice] @ B[K,32] for this CTA's K-slice.
// BM=64, 128 threads (4 warps), BK=64 double-buffered B + register-prefetched
// A frags (direct LDG in mma layout). Small CTAs -> 4+ resident CTAs/SM so
// independent streams hide LDG/barrier latency. Plain-STG partial output.
// ---------------------------------------------------------------------------
__global__ __launch_bounds__(128, 4)
void gemm_mma(const float* __restrict__ A, const float* __restrict__ B,
              float* __restrict__ Cbase, int M, int K, int klen) {
    __shared__ __nv_bfloat16 Bh[2][32 * BSTR];
    __shared__ __nv_bfloat16 Bl[2][32 * BSTR];

    const int tid  = threadIdx.x;
    const int warp = tid >> 5, lane = tid & 31;
    const int g    = lane >> 2, tg = lane & 3;
    const int row0 = blockIdx.x * 64;
    const int kbeg = blockIdx.y * klen;          // klen mult of 64
    const int kend = min(kbeg + klen, K);
    const int nch  = (kend > kbeg) ? ((kend - kbeg + 63) >> 6) : 0;
    const size_t pstride = (size_t)M * NHID;

    const int gr0 = row0 + warp * 16 + g;        // 4 warps x 16 rows = 64
    const bool r0ok = gr0 < M, r8ok = gr0 + 8 < M;
    const float* __restrict__ Ar0 = A + (size_t)gr0 * K;
    const float* __restrict__ Ar8 = Ar0 + (size_t)8 * K;

    const int lt = lane >> 3, lr = lane & 7;
    const uint32_t bh0a = s2u(&Bh[0][0]);
    const uint32_t bl0a = s2u(&Bl[0][0]);
    uint32_t rowoff[2];
#pragma unroll
    for (int p = 0; p < 2; p++)
        rowoff[p] = (uint32_t)(((p * 16 + (lt >> 1) * 8 + lr) * BSTR) * 2 + (lt & 1) * 16);

    float d[4][4];
#pragma unroll
    for (int i = 0; i < 4; i++)
#pragma unroll
        for (int j = 0; j < 4; j++) d[i][j] = 0.f;

    float2   va[16];
    float    vb[16];
    uint32_t ah[4][4], al[4][4];
    const float2 f2z = make_float2(0.f, 0.f);

#define LOADA(k0)                                                              \
    {                                                                          \
        _Pragma("unroll")                                                      \
        for (int ks = 0; ks < 4; ks++) {                                       \
            int gk0 = (k0) + ks * 16 + tg * 2;                                 \
            int gk1 = gk0 + 8;                                                 \
            va[ks*4+0] = (r0ok && gk0 < kend) ? *(const float2*)(Ar0+gk0) : f2z; \
            va[ks*4+1] = (r8ok && gk0 < kend) ? *(const float2*)(Ar8+gk0) : f2z; \
            va[ks*4+2] = (r0ok && gk1 < kend) ? *(const float2*)(Ar0+gk1) : f2z; \
            va[ks*4+3] = (r8ok && gk1 < kend) ? *(const float2*)(Ar8+gk1) : f2z; \
        }                                                                      \
    }

#define LOADB(k0)                                                              \
    {                                                                          \
        _Pragma("unroll")                                                      \
        for (int i = 0; i < 4; i++) {                                          \
            int f = tid + i * 128;           /* [0,512) */                     \
            int n = f & 31, kq = f >> 5;     /* kq in [0,16): k 0..63 */       \
            _Pragma("unroll")                                                  \
            for (int j = 0; j < 4; j++) {                                      \
                int kk = (k0) + kq * 4 + j;                                    \
                vb[i*4+j] = (kk < kend) ? B[(size_t)kk * NHID + n] : 0.f;      \
            }                                                                  \
        }                                                                      \
    }

#define CONVA                                                                  \
    {                                                                          \
        _Pragma("unroll")                                                      \
        for (int ks = 0; ks < 4; ks++)                                         \
            _Pragma("unroll")                                                  \
            for (int j = 0; j < 4; j++)                                        \
                split2(va[ks*4+j].x, va[ks*4+j].y, ah[ks][j], al[ks][j]);      \
    }

#define STSB(bf)                                                               \
    {                                                                          \
        _Pragma("unroll")                                                      \
        for (int i = 0; i < 4; i++) {                                          \
            int f = tid + i * 128;                                             \
            int n = f & 31, kq = f >> 5;                                       \
            uint32_t h0, l0, h1, l1;                                           \
            split2(vb[i*4+0], vb[i*4+1], h0, l0);                              \
            split2(vb[i*4+2], vb[i*4+3], h1, l1);                              \
            int e = n * BSTR + kq * 4;       /* max 2296 < 2304 */             \
            *(uint2*)&Bh[bf][e] = make_uint2(h0, h1);                          \
            *(uint2*)&Bl[bf][e] = make_uint2(l0, l1);                          \
        }                                                                      \
    }

    if (nch > 0) {
        LOADA(kbeg); LOADB(kbeg);
        STSB(0); CONVA;
        __syncthreads();
    }

    for (int c = 0; c < nch; c++) {
        const int  buf  = c & 1;
        const bool more = (c + 1 < nch);
        const int  nk   = kbeg + (c + 1) * 64;
        const uint32_t bha = bh0a + buf * BUFBYTES;
        const uint32_t bla = bl0a + buf * BUFBYTES;

        if (more) { LOADA(nk); LOADB(nk); }   // LDG latency hides behind MMAs

        // ---- compute chunk c: 4 k16-steps x (4 LDSM4 + 12 MMA) ----
#pragma unroll
        for (int ks = 0; ks < 4; ks++) {
            uint32_t bh[2][4], bl[2][4];
#pragma unroll
            for (int p = 0; p < 2; p++) {
                uint32_t ko = (uint32_t)(ks * 32);
                LDSM4(bh[p][0], bh[p][1], bh[p][2], bh[p][3], bha + rowoff[p] + ko);
                LDSM4(bl[p][0], bl[p][1], bl[p][2], bl[p][3], bla + rowoff[p] + ko);
            }
#pragma unroll
            for (int j = 0; j < 4; j++)
                MMA_BF16(d[j], ah[ks], bh[j >> 1][(j & 1) * 2], bh[j >> 1][(j & 1) * 2 + 1]);
#pragma unroll
            for (int j = 0; j < 4; j++)
                MMA_BF16(d[j], ah[ks], bl[j >> 1][(j & 1) * 2], bl[j >> 1][(j & 1) * 2 + 1]);
#pragma unroll
            for (int j = 0; j < 4; j++)
                MMA_BF16(d[j], al[ks], bh[j >> 1][(j & 1) * 2], bh[j >> 1][(j & 1) * 2 + 1]);
        }

        if (more) { STSB(buf ^ 1); CONVA; }
        __syncthreads();
    }

    // ---- epilogue: plain STG into this split's partial buffer ----
    float* __restrict__ Cp = Cbase + (size_t)blockIdx.y * pstride;
#pragma unroll
    for (int nt = 0; nt < 4; nt++) {
        int c0 = nt * 8 + tg * 2;
        if (r0ok)
            *(float2*)&Cp[(size_t)gr0 * NHID + c0] = make_float2(d[nt][0], d[nt][1]);
        if (r8ok)
            *(float2*)&Cp[(size_t)(gr0 + 8) * NHID + c0] = make_float2(d[nt][2], d[nt][3]);
    }
#undef LOADA
#undef LOADB
#undef CONVA
#undef STSB
}

// ---------------------------------------------------------------------------
// Finalize: z = sum of z partials + b (write), student-t q (write).
// 8 lanes per row (4 h-values each), 4 rows per warp.
// ---------------------------------------------------------------------------
__global__ __launch_bounds__(256)
void finalize_kernel(const float* __restrict__ b, const float* __restrict__ mu,
                     float* __restrict__ out) {
    const int lane = threadIdx.x & 31;
    const int warp = (blockIdx.x * blockDim.x + threadIdx.x) >> 5;
    const int row  = warp * 4 + (lane >> 3);
    const int sub  = lane & 7;
    const int hb   = sub * 4;
    if (row >= NROWS) return;

    float4 zv = *(const float4*)&g_z_part[0][(size_t)row * NHID + hb];
#pragma unroll
    for (int p = 1; p < NSPLIT2; p++) {
        float4 t = *(const float4*)&g_z_part[p][(size_t)row * NHID + hb];
        zv.x += t.x; zv.y += t.y; zv.z += t.z; zv.w += t.w;
    }
    {
        float4 bv = *(const float4*)&b[hb];
        zv.x += bv.x; zv.y += bv.y; zv.z += bv.z; zv.w += bv.w;
    }
    *(float4*)&out[(size_t)row * NHID + hb] = zv;

    float d2[KCLUS];
#pragma unroll
    for (int j = 0; j < KCLUS; j++) {
        float4 m = *(const float4*)&mu[j * NHID + hb];
        float dx = zv.x - m.x, dy = zv.y - m.y, dz = zv.z - m.z, dw = zv.w - m.w;
        float v = dx * dx + dy * dy + dz * dz + dw * dw;
        v += __shfl_xor_sync(0xffffffffu, v, 1);
        v += __shfl_xor_sync(0xffffffffu, v, 2);
        v += __shfl_xor_sync(0xffffffffu, v, 4);
        d2[j] = v;
    }

    float qv[KCLUS], ssum = 0.f;
#pragma unroll
    for (int j = 0; j < KCLUS; j++) {
        float base = 1.0f / (1.0f + d2[j] * 5.0f + 1e-8f);  // ALPHA = 0.2
        qv[j] = 0.5f * __powf(base, 1.2f);                  // ^(ALPHA+1) / 2
        ssum += qv[j];
    }
    float inv = 1.0f / ssum;
    float* qrow = out + (size_t)NROWS * NHID + (size_t)row * KCLUS;
    qrow[sub] = qv[sub] * inv;
    if (sub < 2) qrow[8 + sub] = qv[8 + sub] * inv;
}

// ---------------------------------------------------------------------------
extern "C" void kernel_launch(void* const* d_in, const int* in_sizes, int n_in,
                              void* d_out, int out_size) {
    const float* x   = (const float*)d_in[0];  // [10000, 3000]
    const float* adj = (const float*)d_in[1];  // [10000, 10000]
    const float* W   = (const float*)d_in[2];  // [3000, 32]
    const float* b   = (const float*)d_in[3];  // [32]
    const float* mu  = (const float*)d_in[4];  // [10, 32]
    float* out = (float*)d_out;                // z [10000,32] then q [10000,10]

    float *supp, *sup, *zbuf;
    cudaGetSymbolAddress((void**)&supp, g_sup_part);
    cudaGetSymbolAddress((void**)&sup,  g_support);
    cudaGetSymbolAddress((void**)&zbuf, g_z_part);

    // support partials = x @ W : 157 tiles x 3 splits = 471 CTAs (klen 1024)
    {
        dim3 grid(157, NSPLIT1);
        gemm_mma<<<grid, 128>>>(x, W, supp, NROWS, NFEAT, 1024);
    }
    // g_support = sum of 3 partials (L2-resident)
    reduce_sup<<<(NROWS * NHID / 4 + 255) / 256, 256>>>();

    // z partials = adj @ g_support : 157 tiles x 4 splits = 628 CTAs (klen 2560)
    {
        dim3 grid(157, NSPLIT2);
        gemm_mma<<<grid, 128>>>(adj, sup, zbuf, NROWS, NROWS, 2560);
    }
    // bias + partial reduction + soft assignment
    {
        int blocks = (NROWS + 31) / 32;   // 8 warps x 4 rows per block
        finalize_kernel<<<blocks, 256>>>(b, mu, out);
    }
}

// round 14
// speedup vs baseline: 1.3017x; 1.3017x over previous
#include <cuda_runtime.h>
#include <cuda_bf16.h>
#include <cstdint>

#define NROWS 10000
#define NFEAT 3000
#define NHID  32
#define KCLUS 10

#define NSPLIT1 3
#define NSPLIT2 7

#define BSTR 72                       // bf16 elems per B smem row (144 B stride)
#define BUFBYTES (32 * BSTR * 2)      // one B buffer: 4608 B

// Partial-sum scratch (plain STG, no zeroing: every slot overwritten each run)
__device__ __align__(16) float g_sup_part[NSPLIT1][NROWS * NHID];
__device__ __align__(16) float g_support[NROWS * NHID];
__device__ __align__(16) float g_z_part[NSPLIT2][NROWS * NHID];

__device__ __forceinline__ uint32_t s2u(const void* p) {
    uint32_t a;
    asm("{ .reg .u64 t; cvta.to.shared.u64 t, %1; cvt.u32.u64 %0, t; }" : "=r"(a) : "l"(p));
    return a;
}

// fp32 pair -> packed bf16 hi pair + bf16 residual pair
__device__ __forceinline__ void split2(float x, float y, uint32_t& h, uint32_t& l) {
    __nv_bfloat162 hb = __floats2bfloat162_rn(x, y);
    float2 hf = __bfloat1622float2(hb);
    __nv_bfloat162 lb = __floats2bfloat162_rn(x - hf.x, y - hf.y);
    h = *reinterpret_cast<uint32_t*>(&hb);
    l = *reinterpret_cast<uint32_t*>(&lb);
}

#define MMA_BF16(dd, a, b0, b1)                                              \
    asm volatile(                                                            \
        "mma.sync.aligned.m16n8k16.row.col.f32.bf16.bf16.f32 "               \
        "{%0,%1,%2,%3}, {%4,%5,%6,%7}, {%8,%9}, {%0,%1,%2,%3};"              \
        : "+f"(dd[0]), "+f"(dd[1]), "+f"(dd[2]), "+f"(dd[3])                 \
        : "r"(a[0]), "r"(a[1]), "r"(a[2]), "r"(a[3]), "r"(b0), "r"(b1))

#define LDSM4(r0, r1, r2, r3, addr)                                          \
    asm volatile(                                                            \
        "ldmatrix.sync.aligned.m8n8.x4.shared.b16 {%0,%1,%2,%3}, [%4];"      \
        : "=r"(r0), "=r"(r1), "=r"(r2), "=r"(r3) : "r"(addr))

// ---------------------------------------------------------------------------
// g_support = sum of NSPLIT1 gemm1 partials (L2-resident, trivially fast)
// ---------------------------------------------------------------------------
__global__ __launch_bounds__(256)
void reduce_sup() {
    int i = blockIdx.x * blockDim.x + threadIdx.x;
    if (i < (NROWS * NHID) / 4) {
        float4 s = ((const float4*)g_sup_part[0])[i];
#pragma unroll
        for (int p = 1; p < NSPLIT1; p++) {
            float4 t = ((const float4*)g_sup_part[p])[i];
            s.x += t.x; s.y += t.y; s.z += t.z; s.w += t.w;
        }
        ((float4*)g_support)[i] = s;
    }
}

// ---------------------------------------------------------------------------
// Cpart[M,32] = A[M,K_slice] @ B[K,32] (R9-proven geometry: BM=128, 256 thr,
// BK=64). A frags direct from global in mma layout; B via double-buffered
// conflict-free smem + ldmatrix.x4; MMAs grouped by product (4 indep chains).
// Output: plain STG into per-split partial buffer (no atomics, no zeroing).
// ---------------------------------------------------------------------------
__global__ __launch_bounds__(256, 2)
void gemm_mma(const float* __restrict__ A, const float* __restrict__ B,
              float* __restrict__ Cbase, int M, int K, int klen) {
    __shared__ __nv_bfloat16 Bh[2][32 * BSTR];
    __shared__ __nv_bfloat16 Bl[2][32 * BSTR];

    const int tid  = threadIdx.x;
    const int warp = tid >> 5, lane = tid & 31;
    const int g    = lane >> 2, tg = lane & 3;
    const int wm   = warp * 16;
    const int row0 = blockIdx.x * 128;
    const int kbeg = blockIdx.y * klen;          // klen mult of 64
    const int kend = min(kbeg + klen, K);
    const int nch  = (kend > kbeg) ? ((kend - kbeg + 63) >> 6) : 0;
    const size_t pstride = (size_t)M * NHID;

    const int gr0 = row0 + wm + g;
    const bool r0ok = gr0 < M, r8ok = gr0 + 8 < M;
    const float* __restrict__ Ar0 = A + (size_t)gr0 * K;
    const float* __restrict__ Ar8 = Ar0 + (size_t)8 * K;

    const int lt = lane >> 3, lr = lane & 7;
    const uint32_t bh0a = s2u(&Bh[0][0]);
    const uint32_t bl0a = s2u(&Bl[0][0]);
    uint32_t rowoff[2];
#pragma unroll
    for (int p = 0; p < 2; p++)
        rowoff[p] = (uint32_t)(((p * 16 + (lt >> 1) * 8 + lr) * BSTR) * 2 + (lt & 1) * 16);

    float d[4][4];
#pragma unroll
    for (int i = 0; i < 4; i++)
#pragma unroll
        for (int j = 0; j < 4; j++) d[i][j] = 0.f;

    float2   va[16];
    float    vb[8];
    uint32_t ah[4][4], al[4][4];
    const float2 f2z = make_float2(0.f, 0.f);

#define LOADA(k0)                                                              \
    {                                                                          \
        _Pragma("unroll")                                                      \
        for (int ks = 0; ks < 4; ks++) {                                       \
            int gk0 = (k0) + ks * 16 + tg * 2;                                 \
            int gk1 = gk0 + 8;                                                 \
            va[ks*4+0] = (r0ok && gk0 < kend) ? *(const float2*)(Ar0+gk0) : f2z; \
            va[ks*4+1] = (r8ok && gk0 < kend) ? *(const float2*)(Ar8+gk0) : f2z; \
            va[ks*4+2] = (r0ok && gk1 < kend) ? *(const float2*)(Ar0+gk1) : f2z; \
            va[ks*4+3] = (r8ok && gk1 < kend) ? *(const float2*)(Ar8+gk1) : f2z; \
        }                                                                      \
    }

#define LOADB(k0)                                                              \
    {                                                                          \
        _Pragma("unroll")                                                      \
        for (int i = 0; i < 2; i++) {                                          \
            int f = tid + i * 256;                                             \
            int n = f & 31, kq = f >> 5;                                       \
            _Pragma("unroll")                                                  \
            for (int j = 0; j < 4; j++) {                                      \
                int kk = (k0) + kq * 4 + j;                                    \
                vb[i*4+j] = (kk < kend) ? B[(size_t)kk * NHID + n] : 0.f;      \
            }                                                                  \
        }                                                                      \
    }

#define CONVA                                                                  \
    {                                                                          \
        _Pragma("unroll")                                                      \
        for (int ks = 0; ks < 4; ks++)                                         \
            _Pragma("unroll")                                                  \
            for (int j = 0; j < 4; j++)                                        \
                split2(va[ks*4+j].x, va[ks*4+j].y, ah[ks][j], al[ks][j]);      \
    }

#define STSB(bf)                                                               \
    {                                                                          \
        _Pragma("unroll")                                                      \
        for (int i = 0; i < 2; i++) {                                          \
            int f = tid + i * 256;                                             \
            int n = f & 31, kq = f >> 5;                                       \
            uint32_t h0, l0, h1, l1;                                           \
            split2(vb[i*4+0], vb[i*4+1], h0, l0);                              \
            split2(vb[i*4+2], vb[i*4+3], h1, l1);                              \
            int e = n * BSTR + kq * 4;                                         \
            *(uint2*)&Bh[bf][e] = make_uint2(h0, h1);                          \
            *(uint2*)&Bl[bf][e] = make_uint2(l0, l1);                          \
        }                                                                      \
    }

    if (nch > 0) {
        LOADA(kbeg); LOADB(kbeg);
        STSB(0); CONVA;
        __syncthreads();
    }

    for (int c = 0; c < nch; c++) {
        const int  buf  = c & 1;
        const bool more = (c + 1 < nch);
        const int  nk   = kbeg + (c + 1) * 64;
        const uint32_t bha = bh0a + buf * BUFBYTES;
        const uint32_t bla = bl0a + buf * BUFBYTES;

        if (more) { LOADA(nk); LOADB(nk); }   // LDG latency hides behind MMAs

        // ---- compute chunk c: 4 k16-steps x (4 LDSM4 + 12 MMA) ----
#pragma unroll
        for (int ks = 0; ks < 4; ks++) {
            uint32_t bh[2][4], bl[2][4];
#pragma unroll
            for (int p = 0; p < 2; p++) {
                uint32_t ko = (uint32_t)(ks * 32);
                LDSM4(bh[p][0], bh[p][1], bh[p][2], bh[p][3], bha + rowoff[p] + ko);
                LDSM4(bl[p][0], bl[p][1], bl[p][2], bl[p][3], bla + rowoff[p] + ko);
            }
#pragma unroll
            for (int j = 0; j < 4; j++)
                MMA_BF16(d[j], ah[ks], bh[j >> 1][(j & 1) * 2], bh[j >> 1][(j & 1) * 2 + 1]);
#pragma unroll
            for (int j = 0; j < 4; j++)
                MMA_BF16(d[j], ah[ks], bl[j >> 1][(j & 1) * 2], bl[j >> 1][(j & 1) * 2 + 1]);
#pragma unroll
            for (int j = 0; j < 4; j++)
                MMA_BF16(d[j], al[ks], bh[j >> 1][(j & 1) * 2], bh[j >> 1][(j & 1) * 2 + 1]);
        }

        if (more) { STSB(buf ^ 1); CONVA; }
        __syncthreads();
    }

    // ---- epilogue: plain STG into this split's partial buffer ----
    float* __restrict__ Cp = Cbase + (size_t)blockIdx.y * pstride;
#pragma unroll
    for (int nt = 0; nt < 4; nt++) {
        int c0 = nt * 8 + tg * 2;
        if (r0ok)
            *(float2*)&Cp[(size_t)gr0 * NHID + c0] = make_float2(d[nt][0], d[nt][1]);
        if (r8ok)
            *(float2*)&Cp[(size_t)(gr0 + 8) * NHID + c0] = make_float2(d[nt][2], d[nt][3]);
    }
#undef LOADA
#undef LOADB
#undef CONVA
#undef STSB
}

// ---------------------------------------------------------------------------
// Finalize: z = sum of z partials + b (write), student-t q (write).
// 8 lanes per row (4 h-values each), 4 rows per warp.
// ---------------------------------------------------------------------------
__global__ __launch_bounds__(256)
void finalize_kernel(const float* __restrict__ b, const float* __restrict__ mu,
                     float* __restrict__ out) {
    const int lane = threadIdx.x & 31;
    const int warp = (blockIdx.x * blockDim.x + threadIdx.x) >> 5;
    const int row  = warp * 4 + (lane >> 3);
    const int sub  = lane & 7;
    const int hb   = sub * 4;
    if (row >= NROWS) return;

    float4 zv = *(const float4*)&g_z_part[0][(size_t)row * NHID + hb];
#pragma unroll
    for (int p = 1; p < NSPLIT2; p++) {
        float4 t = *(const float4*)&g_z_part[p][(size_t)row * NHID + hb];
        zv.x += t.x; zv.y += t.y; zv.z += t.z; zv.w += t.w;
    }
    {
        float4 bv = *(const float4*)&b[hb];
        zv.x += bv.x; zv.y += bv.y; zv.z += bv.z; zv.w += bv.w;
    }
    *(float4*)&out[(size_t)row * NHID + hb] = zv;

    float d2[KCLUS];
#pragma unroll
    for (int j = 0; j < KCLUS; j++) {
        float4 m = *(const float4*)&mu[j * NHID + hb];
        float dx = zv.x - m.x, dy = zv.y - m.y, dz = zv.z - m.z, dw = zv.w - m.w;
        float v = dx * dx + dy * dy + dz * dz + dw * dw;
        v += __shfl_xor_sync(0xffffffffu, v, 1);
        v += __shfl_xor_sync(0xffffffffu, v, 2);
        v += __shfl_xor_sync(0xffffffffu, v, 4);
        d2[j] = v;
    }

    float qv[KCLUS], ssum = 0.f;
#pragma unroll
    for (int j = 0; j < KCLUS; j++) {
        float base = 1.0f / (1.0f + d2[j] * 5.0f + 1e-8f);  // ALPHA = 0.2
        qv[j] = 0.5f * __powf(base, 1.2f);                  // ^(ALPHA+1) / 2
        ssum += qv[j];
    }
    float inv = 1.0f / ssum;
    float* qrow = out + (size_t)NROWS * NHID + (size_t)row * KCLUS;
    qrow[sub] = qv[sub] * inv;
    if (sub < 2) qrow[8 + sub] = qv[8 + sub] * inv;
}

// ---------------------------------------------------------------------------
extern "C" void kernel_launch(void* const* d_in, const int* in_sizes, int n_in,
                              void* d_out, int out_size) {
    const float* x   = (const float*)d_in[0];  // [10000, 3000]
    const float* adj = (const float*)d_in[1];  // [10000, 10000]
    const float* W   = (const float*)d_in[2];  // [3000, 32]
    const float* b   = (const float*)d_in[3];  // [32]
    const float* mu  = (const float*)d_in[4];  // [10, 32]
    float* out = (float*)d_out;                // z [10000,32] then q [10000,10]

    float *supp, *sup, *zbuf;
    cudaGetSymbolAddress((void**)&supp, g_sup_part);
    cudaGetSymbolAddress((void**)&sup,  g_support);
    cudaGetSymbolAddress((void**)&zbuf, g_z_part);

    // support partials = x @ W : 79 tiles x 3 splits = 237 CTAs (klen 1024)
    {
        dim3 grid(79, NSPLIT1);
        gemm_mma<<<grid, 256>>>(x, W, supp, NROWS, NFEAT, 1024);
    }
    // g_support = sum of 3 partials (L2-resident)
    reduce_sup<<<(NROWS * NHID / 4 + 255) / 256, 256>>>();

    // z partials = adj @ g_support : 79 tiles x 7 splits = 553 CTAs (klen 1472)
    {
        dim3 grid(79, NSPLIT2);
        gemm_mma<<<grid, 256>>>(adj, sup, zbuf, NROWS, NROWS, 1472);
    }
    // bias + partial reduction + soft assignment
    {
        int blocks = (NROWS + 31) / 32;   // 8 warps x 4 rows per block
        finalize_kernel<<<blocks, 256>>>(b, mu, out);
    }
}

// round 15
// speedup vs baseline: 1.4069x; 1.0808x over previous
#include <cuda_runtime.h>
#include <cuda_fp16.h>
#include <cstdint>

#define NROWS 10000
#define NFEAT 3000
#define NHID  32
#define KCLUS 10

#define NSPLIT1 3
#define NSPLIT2 7

#define BSTR 72                       // fp16 elems per B smem row (144 B stride)
#define BUFBYTES (32 * BSTR * 2)      // one B buffer: 4608 B

// Partial-sum scratch (plain STG, no zeroing: every slot overwritten each run)
__device__ __align__(16) float g_sup_part[NSPLIT1][NROWS * NHID];
__device__ __align__(16) float g_support[NROWS * NHID];
__device__ __align__(16) float g_z_part[NSPLIT2][NROWS * NHID];

__device__ __forceinline__ uint32_t s2u(const void* p) {
    uint32_t a;
    asm("{ .reg .u64 t; cvta.to.shared.u64 t, %1; cvt.u32.u64 %0, t; }" : "=r"(a) : "l"(p));
    return a;
}

// fp32 pair (prescaled) -> packed fp16 pair
__device__ __forceinline__ uint32_t cvt2h(float x, float y) {
    __half2 h = __floats2half2_rn(x, y);
    return *reinterpret_cast<uint32_t*>(&h);
}

// fp32 pair (prescaled) -> packed fp16 hi pair + fp16 residual pair
__device__ __forceinline__ void split2h(float x, float y, uint32_t& h, uint32_t& l) {
    __half2 hb = __floats2half2_rn(x, y);
    float2 hf = __half22float2(hb);
    __half2 lb = __floats2half2_rn(x - hf.x, y - hf.y);
    h = *reinterpret_cast<uint32_t*>(&hb);
    l = *reinterpret_cast<uint32_t*>(&lb);
}

#define MMA_F16(dd, a, b0, b1)                                               \
    asm volatile(                                                            \
        "mma.sync.aligned.m16n8k16.row.col.f32.f16.f16.f32 "                 \
        "{%0,%1,%2,%3}, {%4,%5,%6,%7}, {%8,%9}, {%0,%1,%2,%3};"              \
        : "+f"(dd[0]), "+f"(dd[1]), "+f"(dd[2]), "+f"(dd[3])                 \
        : "r"(a[0]), "r"(a[1]), "r"(a[2]), "r"(a[3]), "r"(b0), "r"(b1))

#define LDSM4(r0, r1, r2, r3, addr)                                          \
    asm volatile(                                                            \
        "ldmatrix.sync.aligned.m8n8.x4.shared.b16 {%0,%1,%2,%3}, [%4];"      \
        : "=r"(r0), "=r"(r1), "=r"(r2), "=r"(r3) : "r"(addr))

// ---------------------------------------------------------------------------
// g_support = sum of NSPLIT1 gemm1 partials (L2-resident, trivially fast)
// ---------------------------------------------------------------------------
__global__ __launch_bounds__(256)
void reduce_sup() {
    int i = blockIdx.x * blockDim.x + threadIdx.x;
    if (i < (NROWS * NHID) / 4) {
        float4 s = ((const float4*)g_sup_part[0])[i];
#pragma unroll
        for (int p = 1; p < NSPLIT1; p++) {
            float4 t = ((const float4*)g_sup_part[p])[i];
            s.x += t.x; s.y += t.y; s.z += t.z; s.w += t.w;
        }
        ((float4*)g_support)[i] = s;
    }
}

// ---------------------------------------------------------------------------
// Cpart[M,32] = A[M,K_slice] @ B[K,32] via 2-product fp16 split:
//   C ≈ Ah*(Bh + Bl), A single fp16 (prescaled by as), B split hi/lo
//   (prescaled by bs), output descaled by ds = 1/(as*bs).
// Geometry unchanged from the 140us kernel: BM=128, 256 thr, BK=64,
// A frags direct LDG in mma layout, B double-buffered smem + ldmatrix.x4,
// plain-STG partial outputs.
// ---------------------------------------------------------------------------
__global__ __launch_bounds__(256, 2)
void gemm_mma(const float* __restrict__ A, const float* __restrict__ B,
              float* __restrict__ Cbase, int M, int K, int klen,
              float as, float bs, float ds) {
    __shared__ __half Bh[2][32 * BSTR];
    __shared__ __half Bl[2][32 * BSTR];

    const int tid  = threadIdx.x;
    const int warp = tid >> 5, lane = tid & 31;
    const int g    = lane >> 2, tg = lane & 3;
    const int wm   = warp * 16;
    const int row0 = blockIdx.x * 128;
    const int kbeg = blockIdx.y * klen;          // klen mult of 64
    const int kend = min(kbeg + klen, K);
    const int nch  = (kend > kbeg) ? ((kend - kbeg + 63) >> 6) : 0;
    const size_t pstride = (size_t)M * NHID;

    const int gr0 = row0 + wm + g;
    const bool r0ok = gr0 < M, r8ok = gr0 + 8 < M;
    const float* __restrict__ Ar0 = A + (size_t)gr0 * K;
    const float* __restrict__ Ar8 = Ar0 + (size_t)8 * K;

    const int lt = lane >> 3, lr = lane & 7;
    const uint32_t bh0a = s2u(&Bh[0][0]);
    const uint32_t bl0a = s2u(&Bl[0][0]);
    uint32_t rowoff[2];
#pragma unroll
    for (int p = 0; p < 2; p++)
        rowoff[p] = (uint32_t)(((p * 16 + (lt >> 1) * 8 + lr) * BSTR) * 2 + (lt & 1) * 16);

    float d[4][4];
#pragma unroll
    for (int i = 0; i < 4; i++)
#pragma unroll
        for (int j = 0; j < 4; j++) d[i][j] = 0.f;

    float2   va[16];
    float    vb[8];
    uint32_t ah[4][4];
    const float2 f2z = make_float2(0.f, 0.f);

#define LOADA(k0)                                                              \
    {                                                                          \
        _Pragma("unroll")                                                      \
        for (int ks = 0; ks < 4; ks++) {                                       \
            int gk0 = (k0) + ks * 16 + tg * 2;                                 \
            int gk1 = gk0 + 8;                                                 \
            va[ks*4+0] = (r0ok && gk0 < kend) ? *(const float2*)(Ar0+gk0) : f2z; \
            va[ks*4+1] = (r8ok && gk0 < kend) ? *(const float2*)(Ar8+gk0) : f2z; \
            va[ks*4+2] = (r0ok && gk1 < kend) ? *(const float2*)(Ar0+gk1) : f2z; \
            va[ks*4+3] = (r8ok && gk1 < kend) ? *(const float2*)(Ar8+gk1) : f2z; \
        }                                                                      \
    }

#define LOADB(k0)                                                              \
    {                                                                          \
        _Pragma("unroll")                                                      \
        for (int i = 0; i < 2; i++) {                                          \
            int f = tid + i * 256;                                             \
            int n = f & 31, kq = f >> 5;                                       \
            _Pragma("unroll")                                                  \
            for (int j = 0; j < 4; j++) {                                      \
                int kk = (k0) + kq * 4 + j;                                    \
                vb[i*4+j] = (kk < kend) ? B[(size_t)kk * NHID + n] : 0.f;      \
            }                                                                  \
        }                                                                      \
    }

#define CONVA                                                                  \
    {                                                                          \
        _Pragma("unroll")                                                      \
        for (int ks = 0; ks < 4; ks++)                                         \
            _Pragma("unroll")                                                  \
            for (int j = 0; j < 4; j++)                                        \
                ah[ks][j] = cvt2h(va[ks*4+j].x * as, va[ks*4+j].y * as);       \
    }

#define STSB(bf)                                                               \
    {                                                                          \
        _Pragma("unroll")                                                      \
        for (int i = 0; i < 2; i++) {                                          \
            int f = tid + i * 256;                                             \
            int n = f & 31, kq = f >> 5;                                       \
            uint32_t h0, l0, h1, l1;                                           \
            split2h(vb[i*4+0] * bs, vb[i*4+1] * bs, h0, l0);                   \
            split2h(vb[i*4+2] * bs, vb[i*4+3] * bs, h1, l1);                   \
            int e = n * BSTR + kq * 4;                                         \
            *(uint2*)&Bh[bf][e] = make_uint2(h0, h1);                          \
            *(uint2*)&Bl[bf][e] = make_uint2(l0, l1);                          \
        }                                                                      \
    }

    if (nch > 0) {
        LOADA(kbeg); LOADB(kbeg);
        STSB(0); CONVA;
        __syncthreads();
    }

    for (int c = 0; c < nch; c++) {
        const int  buf  = c & 1;
        const bool more = (c + 1 < nch);
        const int  nk   = kbeg + (c + 1) * 64;
        const uint32_t bha = bh0a + buf * BUFBYTES;
        const uint32_t bla = bl0a + buf * BUFBYTES;

        if (more) { LOADA(nk); LOADB(nk); }   // LDG latency hides behind MMAs

        // ---- compute chunk c: 4 k16-steps x (4 LDSM4 + 8 MMA) ----
#pragma unroll
        for (int ks = 0; ks < 4; ks++) {
            uint32_t bh[2][4], bl[2][4];
#pragma unroll
            for (int p = 0; p < 2; p++) {
                uint32_t ko = (uint32_t)(ks * 32);
                LDSM4(bh[p][0], bh[p][1], bh[p][2], bh[p][3], bha + rowoff[p] + ko);
                LDSM4(bl[p][0], bl[p][1], bl[p][2], bl[p][3], bla + rowoff[p] + ko);
            }
#pragma unroll
            for (int j = 0; j < 4; j++)
                MMA_F16(d[j], ah[ks], bh[j >> 1][(j & 1) * 2], bh[j >> 1][(j & 1) * 2 + 1]);
#pragma unroll
            for (int j = 0; j < 4; j++)
                MMA_F16(d[j], ah[ks], bl[j >> 1][(j & 1) * 2], bl[j >> 1][(j & 1) * 2 + 1]);
        }

        if (more) { STSB(buf ^ 1); CONVA; }
        __syncthreads();
    }

    // ---- epilogue: descale + plain STG into this split's partial buffer ----
    float* __restrict__ Cp = Cbase + (size_t)blockIdx.y * pstride;
#pragma unroll
    for (int nt = 0; nt < 4; nt++) {
        int c0 = nt * 8 + tg * 2;
        if (r0ok)
            *(float2*)&Cp[(size_t)gr0 * NHID + c0] =
                make_float2(d[nt][0] * ds, d[nt][1] * ds);
        if (r8ok)
            *(float2*)&Cp[(size_t)(gr0 + 8) * NHID + c0] =
                make_float2(d[nt][2] * ds, d[nt][3] * ds);
    }
#undef LOADA
#undef LOADB
#undef CONVA
#undef STSB
}

// ---------------------------------------------------------------------------
// Finalize: z = sum of z partials + b (write), student-t q (write).
// 8 lanes per row (4 h-values each), 4 rows per warp.
// ---------------------------------------------------------------------------
__global__ __launch_bounds__(256)
void finalize_kernel(const float* __restrict__ b, const float* __restrict__ mu,
                     float* __restrict__ out) {
    const int lane = threadIdx.x & 31;
    const int warp = (blockIdx.x * blockDim.x + threadIdx.x) >> 5;
    const int row  = warp * 4 + (lane >> 3);
    const int sub  = lane & 7;
    const int hb   = sub * 4;
    if (row >= NROWS) return;

    float4 zv = *(const float4*)&g_z_part[0][(size_t)row * NHID + hb];
#pragma unroll
    for (int p = 1; p < NSPLIT2; p++) {
        float4 t = *(const float4*)&g_z_part[p][(size_t)row * NHID + hb];
        zv.x += t.x; zv.y += t.y; zv.z += t.z; zv.w += t.w;
    }
    {
        float4 bv = *(const float4*)&b[hb];
        zv.x += bv.x; zv.y += bv.y; zv.z += bv.z; zv.w += bv.w;
    }
    *(float4*)&out[(size_t)row * NHID + hb] = zv;

    float d2[KCLUS];
#pragma unroll
    for (int j = 0; j < KCLUS; j++) {
        float4 m = *(const float4*)&mu[j * NHID + hb];
        float dx = zv.x - m.x, dy = zv.y - m.y, dz = zv.z - m.z, dw = zv.w - m.w;
        float v = dx * dx + dy * dy + dz * dz + dw * dw;
        v += __shfl_xor_sync(0xffffffffu, v, 1);
        v += __shfl_xor_sync(0xffffffffu, v, 2);
        v += __shfl_xor_sync(0xffffffffu, v, 4);
        d2[j] = v;
    }

    float qv[KCLUS], ssum = 0.f;
#pragma unroll
    for (int j = 0; j < KCLUS; j++) {
        float base = 1.0f / (1.0f + d2[j] * 5.0f + 1e-8f);  // ALPHA = 0.2
        qv[j] = 0.5f * __powf(base, 1.2f);                  // ^(ALPHA+1) / 2
        ssum += qv[j];
    }
    float inv = 1.0f / ssum;
    float* qrow = out + (size_t)NROWS * NHID + (size_t)row * KCLUS;
    qrow[sub] = qv[sub] * inv;
    if (sub < 2) qrow[8 + sub] = qv[8 + sub] * inv;
}

// ---------------------------------------------------------------------------
extern "C" void kernel_launch(void* const* d_in, const int* in_sizes, int n_in,
                              void* d_out, int out_size) {
    const float* x   = (const float*)d_in[0];  // [10000, 3000]
    const float* adj = (const float*)d_in[1];  // [10000, 10000]
    const float* W   = (const float*)d_in[2];  // [3000, 32]
    const float* b   = (const float*)d_in[3];  // [32]
    const float* mu  = (const float*)d_in[4];  // [10, 32]
    float* out = (float*)d_out;                // z [10000,32] then q [10000,10]

    float *supp, *sup, *zbuf;
    cudaGetSymbolAddress((void**)&supp, g_sup_part);
    cudaGetSymbolAddress((void**)&sup,  g_support);
    cudaGetSymbolAddress((void**)&zbuf, g_z_part);

    // support partials = x @ W : 79 tiles x 3 splits (klen 1024)
    // x ~ N(0,1): as=1; W in ±0.18: bs=32 keeps fp16 residuals normal.
    {
        dim3 grid(79, NSPLIT1);
        gemm_mma<<<grid, 256>>>(x, W, supp, NROWS, NFEAT, 1024,
                                1.0f, 32.0f, 1.0f / 32.0f);
    }
    // g_support = sum of 3 partials (L2-resident)
    reduce_sup<<<(NROWS * NHID / 4 + 255) / 256, 256>>>();

    // z partials = adj @ g_support : 79 tiles x 7 splits (klen 1472)
    // adj in [0,1e-4]: as=8192 lifts out of fp16-subnormal range; bs=32.
    {
        dim3 grid(79, NSPLIT2);
        gemm_mma<<<grid, 256>>>(adj, sup, zbuf, NROWS, NROWS, 1472,
                                8192.0f, 32.0f, 1.0f / (8192.0f * 32.0f));
    }
    // bias + partial reduction + soft assignment
    {
        int blocks = (NROWS + 31) / 32;   // 8 warps x 4 rows per block
        finalize_kernel<<<blocks, 256>>>(b, mu, out);
    }
}

// round 16
// speedup vs baseline: 1.4796x; 1.0517x over previous
#include <cuda_runtime.h>
#include <cuda_fp16.h>
#include <cstdint>

#define NROWS 10000
#define NFEAT 3000
#define NHID  32
#define KCLUS 10

#define NSPLIT1 3
#define NSPLIT2 7

#define BSTR 72                       // fp16 elems per B smem row (144 B stride)
#define BUFBYTES (32 * BSTR * 2)      // one B buffer: 4608 B

// Partial-sum scratch (plain STG, no zeroing: every slot overwritten each run)
__device__ __align__(16) float g_sup_part[NSPLIT1][NROWS * NHID];
__device__ __align__(16) float g_support[NROWS * NHID];
__device__ __align__(16) float g_z_part[NSPLIT2][NROWS * NHID];

__device__ __forceinline__ uint32_t s2u(const void* p) {
    uint32_t a;
    asm("{ .reg .u64 t; cvta.to.shared.u64 t, %1; cvt.u32.u64 %0, t; }" : "=r"(a) : "l"(p));
    return a;
}

// fp32 pair (prescaled) -> packed fp16 pair
__device__ __forceinline__ uint32_t cvt2h(float x, float y) {
    __half2 h = __floats2half2_rn(x, y);
    return *reinterpret_cast<uint32_t*>(&h);
}

#define MMA_F16(dd, a, b0, b1)                                               \
    asm volatile(                                                            \
        "mma.sync.aligned.m16n8k16.row.col.f32.f16.f16.f32 "                 \
        "{%0,%1,%2,%3}, {%4,%5,%6,%7}, {%8,%9}, {%0,%1,%2,%3};"              \
        : "+f"(dd[0]), "+f"(dd[1]), "+f"(dd[2]), "+f"(dd[3])                 \
        : "r"(a[0]), "r"(a[1]), "r"(a[2]), "r"(a[3]), "r"(b0), "r"(b1))

#define LDSM4(r0, r1, r2, r3, addr)                                          \
    asm volatile(                                                            \
        "ldmatrix.sync.aligned.m8n8.x4.shared.b16 {%0,%1,%2,%3}, [%4];"      \
        : "=r"(r0), "=r"(r1), "=r"(r2), "=r"(r3) : "r"(addr))

// ---------------------------------------------------------------------------
// g_support = sum of NSPLIT1 gemm1 partials (L2-resident, trivially fast)
// ---------------------------------------------------------------------------
__global__ __launch_bounds__(256)
void reduce_sup() {
    int i = blockIdx.x * blockDim.x + threadIdx.x;
    if (i < (NROWS * NHID) / 4) {
        float4 s = ((const float4*)g_sup_part[0])[i];
#pragma unroll
        for (int p = 1; p < NSPLIT1; p++) {
            float4 t = ((const float4*)g_sup_part[p])[i];
            s.x += t.x; s.y += t.y; s.z += t.z; s.w += t.w;
        }
        ((float4*)g_support)[i] = s;
    }
}

// ---------------------------------------------------------------------------
// Cpart[M,32] = A[M,K_slice] @ B[K,32], single-product fp16:
//   C ≈ Ah*Bh, A prescaled by as, B prescaled by bs, output descaled by ds.
// Error: A- and B-truncation (each ~2^-11 relative, random-walk over K);
// measured A-only term was 7.2e-5, so both ~1-2e-4 << 1e-3 tolerance.
// Geometry: BM=128, 256 thr, BK=64, A frags direct LDG in mma layout,
// B double-buffered smem + ldmatrix.x4, plain-STG partial outputs.
// ---------------------------------------------------------------------------
__global__ __launch_bounds__(256, 2)
void gemm_mma(const float* __restrict__ A, const float* __restrict__ B,
              float* __restrict__ Cbase, int M, int K, int klen,
              float as, float bs, float ds) {
    __shared__ __half Bh[2][32 * BSTR];

    const int tid  = threadIdx.x;
    const int warp = tid >> 5, lane = tid & 31;
    const int g    = lane >> 2, tg = lane & 3;
    const int wm   = warp * 16;
    const int row0 = blockIdx.x * 128;
    const int kbeg = blockIdx.y * klen;          // klen mult of 64
    const int kend = min(kbeg + klen, K);
    const int nch  = (kend > kbeg) ? ((kend - kbeg + 63) >> 6) : 0;
    const size_t pstride = (size_t)M * NHID;

    const int gr0 = row0 + wm + g;
    const bool r0ok = gr0 < M, r8ok = gr0 + 8 < M;
    const float* __restrict__ Ar0 = A + (size_t)gr0 * K;
    const float* __restrict__ Ar8 = Ar0 + (size_t)8 * K;

    const int lt = lane >> 3, lr = lane & 7;
    const uint32_t bh0a = s2u(&Bh[0][0]);
    uint32_t rowoff[2];
#pragma unroll
    for (int p = 0; p < 2; p++)
        rowoff[p] = (uint32_t)(((p * 16 + (lt >> 1) * 8 + lr) * BSTR) * 2 + (lt & 1) * 16);

    float d[4][4];
#pragma unroll
    for (int i = 0; i < 4; i++)
#pragma unroll
        for (int j = 0; j < 4; j++) d[i][j] = 0.f;

    float2   va[16];
    float    vb[8];
    uint32_t ah[4][4];
    const float2 f2z = make_float2(0.f, 0.f);

#define LOADA(k0)                                                              \
    {                                                                          \
        _Pragma("unroll")                                                      \
        for (int ks = 0; ks < 4; ks++) {                                       \
            int gk0 = (k0) + ks * 16 + tg * 2;                                 \
            int gk1 = gk0 + 8;                                                 \
            va[ks*4+0] = (r0ok && gk0 < kend) ? *(const float2*)(Ar0+gk0) : f2z; \
            va[ks*4+1] = (r8ok && gk0 < kend) ? *(const float2*)(Ar8+gk0) : f2z; \
            va[ks*4+2] = (r0ok && gk1 < kend) ? *(const float2*)(Ar0+gk1) : f2z; \
            va[ks*4+3] = (r8ok && gk1 < kend) ? *(const float2*)(Ar8+gk1) : f2z; \
        }                                                                      \
    }

#define LOADB(k0)                                                              \
    {                                                                          \
        _Pragma("unroll")                                                      \
        for (int i = 0; i < 2; i++) {                                          \
            int f = tid + i * 256;                                             \
            int n = f & 31, kq = f >> 5;                                       \
            _Pragma("unroll")                                                  \
            for (int j = 0; j < 4; j++) {                                      \
                int kk = (k0) + kq * 4 + j;                                    \
                vb[i*4+j] = (kk < kend) ? B[(size_t)kk * NHID + n] : 0.f;      \
            }                                                                  \
        }                                                                      \
    }

#define CONVA                                                                  \
    {                                                                          \
        _Pragma("unroll")                                                      \
        for (int ks = 0; ks < 4; ks++)                                         \
            _Pragma("unroll")                                                  \
            for (int j = 0; j < 4; j++)                                        \
                ah[ks][j] = cvt2h(va[ks*4+j].x * as, va[ks*4+j].y * as);       \
    }

#define STSB(bf)                                                               \
    {                                                                          \
        _Pragma("unroll")                                                      \
        for (int i = 0; i < 2; i++) {                                          \
            int f = tid + i * 256;                                             \
            int n = f & 31, kq = f >> 5;                                       \
            uint32_t h0 = cvt2h(vb[i*4+0] * bs, vb[i*4+1] * bs);               \
            uint32_t h1 = cvt2h(vb[i*4+2] * bs, vb[i*4+3] * bs);               \
            int e = n * BSTR + kq * 4;                                         \
            *(uint2*)&Bh[bf][e] = make_uint2(h0, h1);                          \
        }                                                                      \
    }

    if (nch > 0) {
        LOADA(kbeg); LOADB(kbeg);
        STSB(0); CONVA;
        __syncthreads();
    }

    for (int c = 0; c < nch; c++) {
        const int  buf  = c & 1;
        const bool more = (c + 1 < nch);
        const int  nk   = kbeg + (c + 1) * 64;
        const uint32_t bha = bh0a + buf * BUFBYTES;

        if (more) { LOADA(nk); LOADB(nk); }   // LDG latency hides behind MMAs

        // ---- compute chunk c: 4 k16-steps x (2 LDSM4 + 4 MMA) ----
#pragma unroll
        for (int ks = 0; ks < 4; ks++) {
            uint32_t bh[2][4];
#pragma unroll
            for (int p = 0; p < 2; p++) {
                uint32_t ko = (uint32_t)(ks * 32);
                LDSM4(bh[p][0], bh[p][1], bh[p][2], bh[p][3], bha + rowoff[p] + ko);
            }
#pragma unroll
            for (int j = 0; j < 4; j++)
                MMA_F16(d[j], ah[ks], bh[j >> 1][(j & 1) * 2], bh[j >> 1][(j & 1) * 2 + 1]);
        }

        if (more) { STSB(buf ^ 1); CONVA; }
        __syncthreads();
    }

    // ---- epilogue: descale + plain STG into this split's partial buffer ----
    float* __restrict__ Cp = Cbase + (size_t)blockIdx.y * pstride;
#pragma unroll
    for (int nt = 0; nt < 4; nt++) {
        int c0 = nt * 8 + tg * 2;
        if (r0ok)
            *(float2*)&Cp[(size_t)gr0 * NHID + c0] =
                make_float2(d[nt][0] * ds, d[nt][1] * ds);
        if (r8ok)
            *(float2*)&Cp[(size_t)(gr0 + 8) * NHID + c0] =
                make_float2(d[nt][2] * ds, d[nt][3] * ds);
    }
#undef LOADA
#undef LOADB
#undef CONVA
#undef STSB
}

// ---------------------------------------------------------------------------
// Finalize: z = sum of z partials + b (write), student-t q (write).
// 8 lanes per row (4 h-values each), 4 rows per warp.
// ---------------------------------------------------------------------------
__global__ __launch_bounds__(256)
void finalize_kernel(const float* __restrict__ b, const float* __restrict__ mu,
                     float* __restrict__ out) {
    const int lane = threadIdx.x & 31;
    const int warp = (blockIdx.x * blockDim.x + threadIdx.x) >> 5;
    const int row  = warp * 4 + (lane >> 3);
    const int sub  = lane & 7;
    const int hb   = sub * 4;
    if (row >= NROWS) return;

    float4 zv = *(const float4*)&g_z_part[0][(size_t)row * NHID + hb];
#pragma unroll
    for (int p = 1; p < NSPLIT2; p++) {
        float4 t = *(const float4*)&g_z_part[p][(size_t)row * NHID + hb];
        zv.x += t.x; zv.y += t.y; zv.z += t.z; zv.w += t.w;
    }
    {
        float4 bv = *(const float4*)&b[hb];
        zv.x += bv.x; zv.y += bv.y; zv.z += bv.z; zv.w += bv.w;
    }
    *(float4*)&out[(size_t)row * NHID + hb] = zv;

    float d2[KCLUS];
#pragma unroll
    for (int j = 0; j < KCLUS; j++) {
        float4 m = *(const float4*)&mu[j * NHID + hb];
        float dx = zv.x - m.x, dy = zv.y - m.y, dz = zv.z - m.z, dw = zv.w - m.w;
        float v = dx * dx + dy * dy + dz * dz + dw * dw;
        v += __shfl_xor_sync(0xffffffffu, v, 1);
        v += __shfl_xor_sync(0xffffffffu, v, 2);
        v += __shfl_xor_sync(0xffffffffu, v, 4);
        d2[j] = v;
    }

    float qv[KCLUS], ssum = 0.f;
#pragma unroll
    for (int j = 0; j < KCLUS; j++) {
        float base = 1.0f / (1.0f + d2[j] * 5.0f + 1e-8f);  // ALPHA = 0.2
        qv[j] = 0.5f * __powf(base, 1.2f);                  // ^(ALPHA+1) / 2
        ssum += qv[j];
    }
    float inv = 1.0f / ssum;
    float* qrow = out + (size_t)NROWS * NHID + (size_t)row * KCLUS;
    qrow[sub] = qv[sub] * inv;
    if (sub < 2) qrow[8 + sub] = qv[8 + sub] * inv;
}

// ---------------------------------------------------------------------------
extern "C" void kernel_launch(void* const* d_in, const int* in_sizes, int n_in,
                              void* d_out, int out_size) {
    const float* x   = (const float*)d_in[0];  // [10000, 3000]
    const float* adj = (const float*)d_in[1];  // [10000, 10000]
    const float* W   = (const float*)d_in[2];  // [3000, 32]
    const float* b   = (const float*)d_in[3];  // [32]
    const float* mu  = (const float*)d_in[4];  // [10, 32]
    float* out = (float*)d_out;                // z [10000,32] then q [10000,10]

    float *supp, *sup, *zbuf;
    cudaGetSymbolAddress((void**)&supp, g_sup_part);
    cudaGetSymbolAddress((void**)&sup,  g_support);
    cudaGetSymbolAddress((void**)&zbuf, g_z_part);

    // support partials = x @ W : 79 tiles x 3 splits (klen 1024)
    // x ~ N(0,1): as=1; W in ±0.18: bs=32 keeps fp16 values well-normal.
    {
        dim3 grid(79, NSPLIT1);
        gemm_mma<<<grid, 256>>>(x, W, supp, NROWS, NFEAT, 1024,
                                1.0f, 32.0f, 1.0f / 32.0f);
    }
    // g_support = sum of 3 partials (L2-resident)
    reduce_sup<<<(NROWS * NHID / 4 + 255) / 256, 256>>>();

    // z partials = adj @ g_support : 79 tiles x 7 splits (klen 1472)
    // adj in [0,1e-4]: as=8192 lifts out of fp16-subnormal range; bs=32.
    {
        dim3 grid(79, NSPLIT2);
        gemm_mma<<<grid, 256>>>(adj, sup, zbuf, NROWS, NROWS, 1472,
                                8192.0f, 32.0f, 1.0f / (8192.0f * 32.0f));
    }
    // bias + partial reduction + soft assignment
    {
        int blocks = (NROWS + 31) / 32;   // 8 warps x 4 rows per block
        finalize_kernel<<<blocks, 256>>>(b, mu, out);
    }
}